// round 5
// baseline (speedup 1.0000x reference)
#include <cuda_runtime.h>
#include <math.h>

#define THREADS 256
#define ROWS_PER_BLOCK 64
#define NF 128
#define NG 64
#define NM 3
#define PAD 129
#define CHUNKS 8
#define GPC 8    // groups per chunk (NG / CHUNKS)

#define HALF_LOG_2PI 0.9189385332046727f
#define L2E 1.4426950408889634f
#define LN2 0.6931471805599453f

__device__ float4 gPack[NG * 4];
__device__ int2   gIdx[NG];

__device__ __forceinline__ float ex2f(float x) {
    float y; asm("ex2.approx.ftz.f32 %0, %1;" : "=f"(y) : "f"(x)); return y;
}
__device__ __forceinline__ float lg2f(float x) {
    float y; asm("lg2.approx.ftz.f32 %0, %1;" : "=f"(y) : "f"(x)); return y;
}

// ---- Prep kernel: fold means/stds/sum_weights (+ log-softmax) into per-group
// quadratic coefficients, once. Runs as 1 block of 64 threads.
__global__ void spn_prep_kernel(const int* __restrict__ perm,
                                const float* __restrict__ means,
                                const float* __restrict__ stds,
                                const float* __restrict__ sumw)
{
    const int g = threadIdx.x;
    if (g >= NG) return;
    const int j0 = 2 * g, j1 = 2 * g + 1;
    gIdx[g] = make_int2(perm[j0], perm[j1]);

    float sw0 = sumw[g * 3 + 0];
    float sw1 = sumw[g * 3 + 1];
    float sw2 = sumw[g * 3 + 2];
    float mw  = fmaxf(sw0, fmaxf(sw1, sw2));
    float lse = mw + logf(expf(sw0 - mw) + expf(sw1 - mw) + expf(sw2 - mw));

    float C[3];
    #pragma unroll
    for (int m = 0; m < NM; ++m) {
        float mu0 = means[j0 * 3 + m], sd0 = stds[j0 * 3 + m];
        float mu1 = means[j1 * 3 + m], sd1 = stds[j1 * 3 + m];
        float is0 = 1.0f / sd0;
        float is1 = 1.0f / sd1;
        float is0sq = is0 * is0;
        float is1sq = is1 * is1;
        float a0 = -0.5f * is0sq;
        float b0 = mu0 * is0sq;
        float c0 = -0.5f * mu0 * mu0 * is0sq - logf(sd0) - HALF_LOG_2PI;
        float a1 = -0.5f * is1sq;
        float b1 = mu1 * is1sq;
        float c1 = -0.5f * mu1 * mu1 * is1sq - logf(sd1) - HALF_LOG_2PI;
        float logw = (m == 0 ? sw0 : (m == 1 ? sw1 : sw2)) - lse;
        C[m] = (c0 + c1 + logw) * L2E;
        gPack[g * 4 + m] = make_float4(a0 * L2E, b0 * L2E, a1 * L2E, b1 * L2E);
    }
    gPack[g * 4 + 3] = make_float4(C[0], C[1], C[2], 0.0f);
}

__global__ void __launch_bounds__(THREADS, 5)
spn_kernel(const float* __restrict__ x,
           float* __restrict__ out,
           int B)
{
    // Static smem: 4096 + 512 + 33024 + 2048 = 39680 B (5 blocks/SM fit in 228KB)
    __shared__ float4 sPack[NG * 4];
    __shared__ int2   sIdx[NG];
    __shared__ float  sx[ROWS_PER_BLOCK * PAD];
    __shared__ float  sRed[CHUNKS * ROWS_PER_BLOCK];

    const int t = threadIdx.x;

    // ---- Phase A: copy precomputed coefficients into smem (1 float4/thread)
    sPack[t] = gPack[t];            // 256 threads == NG*4 entries
    if (t < NG) sIdx[t] = gIdx[t];

    // ---- Phase B: stage x tile into padded smem (coalesced LDG.128)
    const int rowBase = blockIdx.x * ROWS_PER_BLOCK;
    const float4* xg = reinterpret_cast<const float4*>(x) + (long long)rowBase * (NF / 4);
    #pragma unroll
    for (int i = 0; i < (ROWS_PER_BLOCK * NF / 4) / THREADS; ++i) {
        int idx = i * THREADS + t;                 // 0 .. 2047
        float4 v4 = xg[idx];
        int r = idx >> 5;                          // 32 float4 per row
        int c = (idx & 31) << 2;
        float* dst = &sx[r * PAD + c];
        dst[0] = v4.x; dst[1] = v4.y; dst[2] = v4.z; dst[3] = v4.w;
    }
    __syncthreads();

    // ---- Phase C: each warp = one chunk of 8 groups; each lane handles 2 rows.
    // Gathers conflict-free: bank = (row + col) mod 32, row = lane (+32).
    const int chunk = t >> 5;
    const int lane  = t & 31;
    const float* xrA = &sx[lane * PAD];
    const float* xrB = &sx[(lane + 32) * PAD];

    float accMA = 0.0f, accLA = 0.0f;
    float accMB = 0.0f, accLB = 0.0f;

    const int gBase = chunk * GPC;

    // Prime the pipeline: iteration 0's index + gathers
    int2 uv = sIdx[gBase];
    float x0a = xrA[uv.x], x1a = xrA[uv.y];
    float x0b = xrB[uv.x], x1b = xrB[uv.y];

    #pragma unroll
    for (int i = 0; i < GPC; ++i) {
        // Prefetch next iteration's critical chain (sIdx -> gathers).
        // Last iteration wraps to gBase: harmless redundant loads, branch-free.
        const int gn = gBase + ((i + 1) & (GPC - 1));
        int2 nuv = sIdx[gn];
        float nx0a = xrA[nuv.x], nx1a = xrA[nuv.y];
        float nx0b = xrB[nuv.x], nx1b = xrB[nuv.y];

        const int g = gBase + i;
        float4 k0 = sPack[g * 4 + 0];
        float4 k1 = sPack[g * 4 + 1];
        float4 k2 = sPack[g * 4 + 2];
        float4 kc = sPack[g * 4 + 3];

        // Row A
        {
            float p0 = fmaf(fmaf(k0.z, x1a, k0.w), x1a, fmaf(fmaf(k0.x, x0a, k0.y), x0a, kc.x));
            float p1 = fmaf(fmaf(k1.z, x1a, k1.w), x1a, fmaf(fmaf(k1.x, x0a, k1.y), x0a, kc.y));
            float p2 = fmaf(fmaf(k2.z, x1a, k2.w), x1a, fmaf(fmaf(k2.x, x0a, k2.y), x0a, kc.z));
            float mx = fmaxf(p0, fmaxf(p1, p2));
            float s  = ex2f(p0 - mx) + ex2f(p1 - mx) + ex2f(p2 - mx);
            accMA += mx;
            accLA += lg2f(s);
        }
        // Row B
        {
            float p0 = fmaf(fmaf(k0.z, x1b, k0.w), x1b, fmaf(fmaf(k0.x, x0b, k0.y), x0b, kc.x));
            float p1 = fmaf(fmaf(k1.z, x1b, k1.w), x1b, fmaf(fmaf(k1.x, x0b, k1.y), x0b, kc.y));
            float p2 = fmaf(fmaf(k2.z, x1b, k2.w), x1b, fmaf(fmaf(k2.x, x0b, k2.y), x0b, kc.z));
            float mx = fmaxf(p0, fmaxf(p1, p2));
            float s  = ex2f(p0 - mx) + ex2f(p1 - mx) + ex2f(p2 - mx);
            accMB += mx;
            accLB += lg2f(s);
        }

        x0a = nx0a; x1a = nx1a;
        x0b = nx0b; x1b = nx1b;
    }

    sRed[chunk * ROWS_PER_BLOCK + lane]      = accMA + accLA;
    sRed[chunk * ROWS_PER_BLOCK + lane + 32] = accMB + accLB;
    __syncthreads();

    // ---- Phase D: threads 0..63 combine the 8 chunk partials per row
    if (t < ROWS_PER_BLOCK) {
        float v = 0.0f;
        #pragma unroll
        for (int c = 0; c < CHUNKS; ++c)
            v += sRed[c * ROWS_PER_BLOCK + t];
        int gRow = rowBase + t;
        if (gRow < B) out[gRow] = v * LN2;
    }
}

extern "C" void kernel_launch(void* const* d_in, const int* in_sizes, int n_in,
                              void* d_out, int out_size)
{
    const float* x     = (const float*)d_in[0];
    const int*   perm  = (const int*)d_in[1];
    const float* means = (const float*)d_in[2];
    const float* stds  = (const float*)d_in[3];
    const float* sumw  = (const float*)d_in[4];
    float* out = (float*)d_out;

    int B = in_sizes[0] / NF;

    spn_prep_kernel<<<1, 64>>>(perm, means, stds, sumw);

    dim3 grid((B + ROWS_PER_BLOCK - 1) / ROWS_PER_BLOCK);
    spn_kernel<<<grid, THREADS>>>(x, out, B);
}